// round 1
// baseline (speedup 1.0000x reference)
#include <cuda_runtime.h>
#include <stdint.h>

// Problem constants
#define Bb    512
#define Nn    40
#define Hh    128
#define FEe   16
#define Mm    128
#define NPASS 3
#define NOUT  128
#define NODES (Bb * Nn)   // 20480

// ------------------------- device scratch (no cudaMalloc allowed) ------------
__device__ float g_h   [NODES * Hh];          // current hidden state
__device__ float g_proj[NODES * 2 * Mm];      // [nghb_proj | emb] per node
__device__ float g_msg [NODES * Mm];          // messages
__device__ float g_gi  [NODES * 3 * Hh];      // msg @ Wi
__device__ float g_gh  [NODES * 3 * Hh];      // h   @ Wh
__device__ float g_xr  [NODES * 2 * Hh];      // [h | nodes] for readout
__device__ float g_R   [NODES * 2 * NOUT];    // readout GEMM result
__device__ float g_Wpr [Hh * 2 * Mm];         // [Wn | Wm]  (128 x 256)
__device__ float g_Wro [2 * Hh * 2 * NOUT];   // [Wg | Wo]  (256 x 256)
__device__ float g_ec  [NODES * Nn * FEe];    // compacted edge features
__device__ int   g_nbr [NODES * Nn];          // compact neighbor indices
__device__ int   g_ncnt[NODES];               // neighbor counts

// ------------------------- math helpers --------------------------------------
__device__ __forceinline__ float tanh_acc(float x) {
    float e = __expf(2.0f * x);          // MUFU.EX2, accurate enough (~2^-22)
    return 1.0f - 2.0f / (e + 1.0f);     // inf -> 1, 0 -> -1 handled naturally
}
__device__ __forceinline__ float sigmoid_acc(float x) {
    return 1.0f / (1.0f + __expf(-x));
}

// ------------------------- prep: combined weights + xr nodes copy ------------
__global__ void prep_misc(const float* __restrict__ Wn, const float* __restrict__ Wm,
                          const float* __restrict__ Wg, const float* __restrict__ Wo,
                          const float* __restrict__ nodes) {
    int idx = blockIdx.x * blockDim.x + threadIdx.x;
    if (idx < Hh * 2 * Mm) {             // Wpr = [Wn | Wm]
        int k = idx >> 8, c = idx & 255;
        g_Wpr[idx] = (c < Mm) ? Wn[k * Mm + c] : Wm[k * Mm + (c - Mm)];
    }
    if (idx < 2 * Hh * 2 * NOUT) {       // Wro = [Wg | Wo]
        int k = idx >> 8, c = idx & 255;
        g_Wro[idx] = (c < NOUT) ? Wg[k * NOUT + c] : Wo[k * NOUT + (c - NOUT)];
    }
    if (idx < NODES * Hh) {              // xr[:,128:256] = nodes
        int node = idx >> 7, c = idx & 127;
        g_xr[node * 2 * Hh + Hh + c] = nodes[idx];
    }
}

// ------------------------- prep: neighbor compaction -------------------------
__global__ void prep_graph(const float* __restrict__ edges) {
    int bi = blockIdx.x;                      // node id 0..NODES-1
    const float* erow = edges + (size_t)bi * (Nn * FEe);
    __shared__ float ssum[Nn];
    __shared__ int   slist[Nn];
    __shared__ int   snc;
    int t = threadIdx.x;                      // 64 threads
    if (t < Nn) {
        const float4* p = (const float4*)(erow + t * FEe);
        float s = 0.f;
        #pragma unroll
        for (int q = 0; q < 4; q++) { float4 v = p[q]; s += v.x + v.y + v.z + v.w; }
        ssum[t] = s;
    }
    __syncthreads();
    if (t == 0) {                             // deterministic serial compaction
        int c = 0;
        for (int j = 0; j < Nn; j++) if (ssum[j] > 0.f) slist[c++] = j;
        snc = c; g_ncnt[bi] = c;
    }
    __syncthreads();
    int nc = snc;
    if (t < nc) g_nbr[bi * Nn + t] = slist[t];
    // copy compact features (float4 granularity: FE=16 -> 4 float4 per edge)
    float4* dst = (float4*)(g_ec + (size_t)bi * Nn * FEe);
    for (int idx = t; idx < nc * 4; idx += blockDim.x) {
        int k = idx >> 2, q = idx & 3;
        dst[idx] = ((const float4*)(erow + slist[k] * FEe))[q];
    }
}

// ------------------------- fused attention + messages ------------------------
// block = one (b,i) node, 128 threads (one per m). Single-loop softmax
// (tanh output is in [-1,1] so no running max needed).
__global__ void attn_kernel(const float* __restrict__ We) {
    int bi = blockIdx.x;
    int m  = threadIdx.x;
    int b  = bi / Nn;
    int nc = g_ncnt[bi];
    if (nc == 0) { g_msg[bi * Mm + m] = 0.0f; return; }

    __shared__ __align__(16) float ef[Nn][FEe];
    __shared__ int jl[Nn];
    const float4* src = (const float4*)(g_ec + (size_t)bi * Nn * FEe);
    float4* efv = (float4*)&ef[0][0];
    for (int idx = m; idx < nc * 4; idx += blockDim.x) efv[idx] = src[idx];
    if (m < nc) jl[m] = g_nbr[bi * Nn + m];
    __syncthreads();

    float we[FEe];
    #pragma unroll
    for (int f = 0; f < FEe; f++) we[f] = We[f * Mm + m];

    const float* projb = g_proj + (size_t)b * Nn * 2 * Mm;
    float s = 0.0f, acc = 0.0f;
    for (int k = 0; k < nc; k++) {
        int j = jl[k];
        float nb = projb[j * 2 * Mm + m];
        float em = projb[j * 2 * Mm + Mm + m];
        float x = nb;
        #pragma unroll
        for (int f = 0; f < FEe; f++) x = fmaf(ef[k][f], we[f], x);
        float tt = tanh_acc(x);
        float p  = __expf(tt);
        s += p;
        acc = fmaf(p, em, acc);
    }
    g_msg[bi * Mm + m] = acc / s;
}

// ------------------------- generic fp32 SGEMM --------------------------------
// C[Mr x N] = A[Mr x K] @ W[K x N], row-major. Mr%128==0, N%128==0, K%8==0.
// 128x128 block tile, BK=8, 256 threads, 8x8 micro-tile (4+4 split fragments),
// double-buffered smem. blockIdx.z selects (A,W,C) set 0 or 1 (fused dual GEMM).
__global__ __launch_bounds__(256) void sgemm128(
    const float* A0, const float* W0, float* C0,
    const float* A1, const float* W1, float* C1,
    int K, int N)
{
    const float* A = blockIdx.z ? A1 : A0;
    const float* W = blockIdx.z ? W1 : W0;
    float*       C = blockIdx.z ? C1 : C0;

    __shared__ float As[2][8][128];
    __shared__ float Bs[2][8][128];

    int tid  = threadIdx.x;
    int brow = blockIdx.y * 128;
    int bcol = blockIdx.x * 128;

    int arow = tid >> 1;            // 0..127
    int acol = (tid & 1) * 4;       // 0 or 4
    int wrow = tid >> 5;            // 0..7
    int wcol = (tid & 31) * 4;      // 0..124

    int ty = tid >> 4;              // 0..15
    int tx = tid & 15;              // 0..15

    float acc[8][8];
    #pragma unroll
    for (int i = 0; i < 8; i++)
        #pragma unroll
        for (int j = 0; j < 8; j++) acc[i][j] = 0.0f;

    // preload tile 0
    {
        float4 av = *(const float4*)(A + (size_t)(brow + arow) * K + acol);
        As[0][acol + 0][arow] = av.x; As[0][acol + 1][arow] = av.y;
        As[0][acol + 2][arow] = av.z; As[0][acol + 3][arow] = av.w;
        float4 wv = *(const float4*)(W + (size_t)wrow * N + bcol + wcol);
        *(float4*)&Bs[0][wrow][wcol] = wv;
    }
    __syncthreads();

    int nk = K >> 3;
    for (int t = 0; t < nk; t++) {
        int cur = t & 1, nxt = cur ^ 1;
        if (t + 1 < nk) {
            int k0 = (t + 1) * 8;
            float4 av = *(const float4*)(A + (size_t)(brow + arow) * K + k0 + acol);
            As[nxt][acol + 0][arow] = av.x; As[nxt][acol + 1][arow] = av.y;
            As[nxt][acol + 2][arow] = av.z; As[nxt][acol + 3][arow] = av.w;
            float4 wv = *(const float4*)(W + (size_t)(k0 + wrow) * N + bcol + wcol);
            *(float4*)&Bs[nxt][wrow][wcol] = wv;
        }
        #pragma unroll
        for (int kk = 0; kk < 8; kk++) {
            float ar[8], br[8];
            float4 a0 = *(const float4*)&As[cur][kk][ty * 4];
            float4 a1 = *(const float4*)&As[cur][kk][64 + ty * 4];
            float4 b0 = *(const float4*)&Bs[cur][kk][tx * 4];
            float4 b1 = *(const float4*)&Bs[cur][kk][64 + tx * 4];
            ar[0]=a0.x; ar[1]=a0.y; ar[2]=a0.z; ar[3]=a0.w;
            ar[4]=a1.x; ar[5]=a1.y; ar[6]=a1.z; ar[7]=a1.w;
            br[0]=b0.x; br[1]=b0.y; br[2]=b0.z; br[3]=b0.w;
            br[4]=b1.x; br[5]=b1.y; br[6]=b1.z; br[7]=b1.w;
            #pragma unroll
            for (int i = 0; i < 8; i++)
                #pragma unroll
                for (int j = 0; j < 8; j++)
                    acc[i][j] = fmaf(ar[i], br[j], acc[i][j]);
        }
        __syncthreads();
    }

    #pragma unroll
    for (int i = 0; i < 8; i++) {
        int row = brow + ((i < 4) ? (ty * 4 + i) : (64 + ty * 4 + i - 4));
        float4* c0 = (float4*)(C + (size_t)row * N + bcol + tx * 4);
        float4* c1 = (float4*)(C + (size_t)row * N + bcol + 64 + tx * 4);
        *c0 = make_float4(acc[i][0], acc[i][1], acc[i][2], acc[i][3]);
        *c1 = make_float4(acc[i][4], acc[i][5], acc[i][6], acc[i][7]);
    }
}

// ------------------------- GRU elementwise -----------------------------------
__global__ void gru_kernel(const float* __restrict__ hprev,
                           const float* __restrict__ bi_, const float* __restrict__ bh_,
                           int last) {
    int node = blockIdx.x;
    int t    = threadIdx.x;
    float hv = hprev[(size_t)node * Hh + t];
    if (g_ncnt[node] > 0) {
        size_t base = (size_t)node * 3 * Hh;
        float gr  = g_gi[base + t]            + bi_[t]            + g_gh[base + t]            + bh_[t];
        float gz  = g_gi[base + Hh + t]       + bi_[Hh + t]       + g_gh[base + Hh + t]       + bh_[Hh + t];
        float gin = g_gi[base + 2 * Hh + t]   + bi_[2 * Hh + t];
        float ghn = g_gh[base + 2 * Hh + t]   + bh_[2 * Hh + t];
        float r = sigmoid_acc(gr);
        float z = sigmoid_acc(gz);
        float n = tanh_acc(fmaf(r, ghn, gin));
        hv = (1.0f - z) * n + z * hv;
    }
    g_h[(size_t)node * Hh + t] = hv;
    if (last) g_xr[(size_t)node * 2 * Hh + t] = hv;
}

// ------------------------- gated readout reduction ---------------------------
__global__ void readout_kernel(const float* __restrict__ bg, const float* __restrict__ bo,
                               float* __restrict__ out) {
    int b = blockIdx.x;
    int o = threadIdx.x;
    float acc = 0.0f;
    for (int i = 0; i < Nn; i++) {
        int node = b * Nn + i;
        if (g_ncnt[node] > 0) {
            float g = g_R[(size_t)node * 2 * NOUT + o]        + bg[o];
            float e = g_R[(size_t)node * 2 * NOUT + NOUT + o] + bo[o];
            acc = fmaf(sigmoid_acc(g), e, acc);
        }
    }
    out[(size_t)b * NOUT + o] = acc;
}

// ------------------------- host orchestration --------------------------------
extern "C" void kernel_launch(void* const* d_in, const int* in_sizes, int n_in,
                              void* d_out, int out_size) {
    const float* nodes = (const float*)d_in[0];
    const float* edges = (const float*)d_in[1];
    const float* We    = (const float*)d_in[2];
    const float* Wn    = (const float*)d_in[3];
    const float* Wm    = (const float*)d_in[4];
    const float* Wi    = (const float*)d_in[5];
    const float* Wh    = (const float*)d_in[6];
    const float* bi_   = (const float*)d_in[7];
    const float* bh_   = (const float*)d_in[8];
    const float* Wg    = (const float*)d_in[9];
    const float* bg    = (const float*)d_in[10];
    const float* Wo    = (const float*)d_in[11];
    const float* bo    = (const float*)d_in[12];
    float* out = (float*)d_out;

    float *p_h, *p_proj, *p_msg, *p_gi, *p_gh, *p_xr, *p_R, *p_Wpr, *p_Wro;
    cudaGetSymbolAddress((void**)&p_h,    g_h);
    cudaGetSymbolAddress((void**)&p_proj, g_proj);
    cudaGetSymbolAddress((void**)&p_msg,  g_msg);
    cudaGetSymbolAddress((void**)&p_gi,   g_gi);
    cudaGetSymbolAddress((void**)&p_gh,   g_gh);
    cudaGetSymbolAddress((void**)&p_xr,   g_xr);
    cudaGetSymbolAddress((void**)&p_R,    g_R);
    cudaGetSymbolAddress((void**)&p_Wpr,  g_Wpr);
    cudaGetSymbolAddress((void**)&p_Wro,  g_Wro);

    // prep
    prep_misc<<<(NODES * Hh + 255) / 256, 256>>>(Wn, Wm, Wg, Wo, nodes);
    prep_graph<<<NODES, 64>>>(edges);

    const int ROWB = NODES / 128;  // 160
    // initial projection: proj = nodes @ [Wn|Wm]
    {
        dim3 g(2 * Mm / 128, ROWB, 1);
        sgemm128<<<g, 256>>>(nodes, p_Wpr, p_proj, nodes, p_Wpr, p_proj, Hh, 2 * Mm);
    }

    const float* hsrc = nodes;
    for (int p = 0; p < NPASS; p++) {
        attn_kernel<<<NODES, 128>>>(We);
        {   // gi = msg @ Wi  (z=0)   gh = h @ Wh  (z=1)
            dim3 g(3 * Hh / 128, ROWB, 2);
            sgemm128<<<g, 256>>>(p_msg, Wi, p_gi, hsrc, Wh, p_gh, Hh, 3 * Hh);
        }
        gru_kernel<<<NODES, 128>>>(hsrc, bi_, bh_, (p == NPASS - 1) ? 1 : 0);
        hsrc = p_h;
        if (p < NPASS - 1) {
            dim3 g(2 * Mm / 128, ROWB, 1);
            sgemm128<<<g, 256>>>(hsrc, p_Wpr, p_proj, hsrc, p_Wpr, p_proj, Hh, 2 * Mm);
        }
    }

    // readout GEMM: R = [h|nodes] @ [Wg|Wo]
    {
        dim3 g(2 * NOUT / 128, ROWB, 1);
        sgemm128<<<g, 256>>>(p_xr, p_Wro, p_R, p_xr, p_Wro, p_R, 2 * Hh, 2 * NOUT);
    }
    readout_kernel<<<Bb, 128>>>(bg, bo, out);
    (void)in_sizes; (void)n_in; (void)out_size;
}

// round 4
// speedup vs baseline: 1.5562x; 1.5562x over previous
#include <cuda_runtime.h>
#include <cuda_bf16.h>
#include <stdint.h>

#define Bb    512
#define Nn    40
#define Hh    128
#define FEe   16
#define Mm    128
#define NPASS 3
#define NOUT  128
#define NODES (Bb * Nn)   // 20480

// ------------------------- device scratch ------------------------------------
__device__ float g_h   [NODES * Hh];
__device__ float g_proj[NODES * 2 * Mm];
__device__ float g_msg [NODES * Mm];
__device__ float g_gi  [NODES * 3 * Hh];
__device__ float g_gh  [NODES * 3 * Hh];
__device__ float g_xr  [NODES * 2 * Hh];
__device__ float g_R   [NODES * 2 * NOUT];
__device__ float g_ec  [NODES * Nn * FEe];
__device__ int   g_nbr [NODES * Nn];
__device__ int   g_ncnt[NODES];
// pre-split, pre-transposed bf16 weight images.
// Per 128x128 tile: [hi: n-major [128n][128k]] [lo: same] = 32768 bf16.
__device__ __nv_bfloat16 g_Wpr_img[2 * 32768];      // [ntile=2]
__device__ __nv_bfloat16 g_Wih_img[2 * 3 * 32768];  // [z=2][ntile=3]
__device__ __nv_bfloat16 g_Wro_img[2 * 2 * 32768];  // [ntile=2][kc=2]

// ------------------------- helpers -------------------------------------------
__device__ __forceinline__ uint32_t smem_u32(const void* p) {
    uint32_t a;
    asm("{ .reg .u64 t; cvta.to.shared.u64 t, %1; cvt.u32.u64 %0, t; }" : "=r"(a) : "l"(p));
    return a;
}
__device__ __forceinline__ void split2(float x, uint16_t& h, uint16_t& l) {
    __nv_bfloat16 hb = __float2bfloat16_rn(x);
    __nv_bfloat16 lb = __float2bfloat16_rn(x - __bfloat162float(hb));
    h = __bfloat16_as_ushort(hb); l = __bfloat16_as_ushort(lb);
}
__device__ __forceinline__ float tanh_f(float x) {
    float e = __expf(2.0f * x);
    return 1.0f - __fdividef(2.0f, e + 1.0f);
}
__device__ __forceinline__ float sigm_f(float x) {
    return __fdividef(1.0f, 1.0f + __expf(-x));
}
__device__ __forceinline__ void ldm4(uint32_t* r, uint32_t addr) {
    asm volatile("ldmatrix.sync.aligned.m8n8.x4.shared.b16 {%0,%1,%2,%3}, [%4];"
                 : "=r"(r[0]), "=r"(r[1]), "=r"(r[2]), "=r"(r[3]) : "r"(addr));
}
__device__ __forceinline__ void mma16816(float* d, const uint32_t* a, uint32_t b0, uint32_t b1) {
    asm volatile(
        "mma.sync.aligned.m16n8k16.row.col.f32.bf16.bf16.f32 "
        "{%0,%1,%2,%3}, {%4,%5,%6,%7}, {%8,%9}, {%0,%1,%2,%3};\n"
        : "+f"(d[0]), "+f"(d[1]), "+f"(d[2]), "+f"(d[3])
        : "r"(a[0]), "r"(a[1]), "r"(a[2]), "r"(a[3]), "r"(b0), "r"(b1));
}

// ------------------------- prep kernels --------------------------------------
__global__ void prep_xr(const float* __restrict__ nodes) {
    int idx = blockIdx.x * blockDim.x + threadIdx.x;
    if (idx < NODES * Hh) {
        int node = idx >> 7, c = idx & 127;
        g_xr[node * 2 * Hh + Hh + c] = nodes[idx];
    }
}
// images: dst[tile*32768 + nl*128 + kl] (hi), +16384 (lo); value = W[k][n]
__global__ void prep_wpr(const float* __restrict__ Wn, const float* __restrict__ Wm) {
    int idx = blockIdx.x * blockDim.x + threadIdx.x;   // 2*16384
    int t = idx >> 14, e = idx & 16383;
    int nl = e >> 7, kl = e & 127;
    float x = (t == 0) ? Wn[kl * Mm + nl] : Wm[kl * Mm + nl];
    uint16_t h, l; split2(x, h, l);
    uint16_t* base = (uint16_t*)(g_Wpr_img + (size_t)t * 32768);
    base[nl * 128 + kl] = h;
    base[16384 + nl * 128 + kl] = l;
}
__global__ void prep_wih(const float* __restrict__ Wi, const float* __restrict__ Wh) {
    int idx = blockIdx.x * blockDim.x + threadIdx.x;   // 2*3*16384
    int z = idx / (3 * 16384), r = idx % (3 * 16384);
    int t = r >> 14, e = r & 16383;
    int nl = e >> 7, kl = e & 127;
    const float* W = z ? Wh : Wi;
    float x = W[kl * 384 + t * 128 + nl];
    uint16_t h, l; split2(x, h, l);
    uint16_t* base = (uint16_t*)(g_Wih_img + (size_t)(z * 3 + t) * 32768);
    base[nl * 128 + kl] = h;
    base[16384 + nl * 128 + kl] = l;
}
__global__ void prep_wro(const float* __restrict__ Wg, const float* __restrict__ Wo) {
    int idx = blockIdx.x * blockDim.x + threadIdx.x;   // 2*2*16384
    int t = idx >> 15, rem = idx & 32767;
    int kc = rem >> 14, e = rem & 16383;
    int nl = e >> 7, kl = e & 127;
    int k = kc * 128 + kl;
    float x = (t == 0) ? Wg[k * NOUT + nl] : Wo[k * NOUT + nl];
    uint16_t h, l; split2(x, h, l);
    uint16_t* base = (uint16_t*)(g_Wro_img + (size_t)(t * 2 + kc) * 32768);
    base[nl * 128 + kl] = h;
    base[16384 + nl * 128 + kl] = l;
}

__global__ void prep_graph(const float* __restrict__ edges) {
    int bi = blockIdx.x;
    const float* erow = edges + (size_t)bi * (Nn * FEe);
    __shared__ float ssum[Nn];
    __shared__ int   slist[Nn];
    __shared__ int   snc;
    int t = threadIdx.x;                      // 64 threads
    if (t < Nn) {
        const float4* p = (const float4*)(erow + t * FEe);
        float s = 0.f;
        #pragma unroll
        for (int q = 0; q < 4; q++) { float4 v = p[q]; s += v.x + v.y + v.z + v.w; }
        ssum[t] = s;
    }
    __syncthreads();
    if (t == 0) {
        int c = 0;
        for (int j = 0; j < Nn; j++) if (ssum[j] > 0.f) slist[c++] = j;
        snc = c; g_ncnt[bi] = c;
    }
    __syncthreads();
    int nc = snc;
    if (t < nc) g_nbr[bi * Nn + t] = slist[t];
    float4* dst = (float4*)(g_ec + (size_t)bi * Nn * FEe);
    for (int idx = t; idx < nc * 4; idx += blockDim.x) {
        int k = idx >> 2, q = idx & 3;
        dst[idx] = ((const float4*)(erow + slist[k] * FEe))[q];
    }
}

// ------------------------- fused attention + messages ------------------------
__global__ void attn_kernel(const float* __restrict__ We) {
    int bi = blockIdx.x;
    int m  = threadIdx.x;
    int b  = bi / Nn;
    int nc = g_ncnt[bi];
    if (nc == 0) { g_msg[bi * Mm + m] = 0.0f; return; }

    __shared__ __align__(16) float ef[Nn][FEe];
    __shared__ int jl[Nn];
    const float4* src = (const float4*)(g_ec + (size_t)bi * Nn * FEe);
    float4* efv = (float4*)&ef[0][0];
    for (int idx = m; idx < nc * 4; idx += blockDim.x) efv[idx] = src[idx];
    if (m < nc) jl[m] = g_nbr[bi * Nn + m];
    __syncthreads();

    float we[FEe];
    #pragma unroll
    for (int f = 0; f < FEe; f++) we[f] = We[f * Mm + m];

    const float* projb = g_proj + (size_t)b * Nn * 2 * Mm;
    float s = 0.0f, acc = 0.0f;
    #pragma unroll 2
    for (int k = 0; k < nc; k++) {
        int j = jl[k];
        float nb = __ldg(projb + j * 2 * Mm + m);
        float em = __ldg(projb + j * 2 * Mm + Mm + m);
        float x = nb;
        #pragma unroll
        for (int f = 0; f < FEe; f++) x = fmaf(ef[k][f], we[f], x);
        float tt = tanh_f(x);
        float p  = __expf(tt);
        s += p;
        acc = fmaf(p, em, acc);
    }
    g_msg[bi * Mm + m] = __fdividef(acc, s);
}

// ------------------------- HMMA split-bf16 GEMM -------------------------------
// C tile (128M x 128N) = A[., K] @ W(images), fp32 accumulate.
// 256 thr, warp grid 4(M) x 2(N), per-warp 32x64, mma.m16n8k16 bf16.
// smem: padded pitch 136 bf16 (272B) -> conflict-free ldmatrix, no swizzle.
#define PITCH 136
#define TILEB (128 * PITCH * 2)          // 34816 bytes per buffer
#define SM_AHI 0
#define SM_ALO (TILEB)
#define SM_BHI (2 * TILEB)
#define SM_BLO (3 * TILEB)
#define GEMM_SMEM (4 * TILEB)            // 139264

__global__ __launch_bounds__(256) void gemm_tc(
    const float* A0, const float* A1, float* C0, float* C1,
    const __nv_bfloat16* img0, const __nv_bfloat16* img1,
    int K, int ldc)
{
    extern __shared__ char smem[];
    const float* A = blockIdx.z ? A1 : A0;
    float*       C = blockIdx.z ? C1 : C0;
    const __nv_bfloat16* img = blockIdx.z ? img1 : img0;

    uint32_t sb = smem_u32(smem);
    int tid = threadIdx.x, wid = tid >> 5, lane = tid & 31;
    int brow = blockIdx.y * 128;
    int ntile = blockIdx.x;
    int kchunks = K >> 7;

    int m0w = (wid & 3) * 32;        // warp M offset
    int n0w = (wid >> 2) * 64;       // warp N offset

    // ldmatrix per-lane offsets (bytes), relative to buffer base
    int q = lane >> 3, r = lane & 7;
    // A: tile q -> (q&1)*8 rows, (q>>1)*8 cols
    uint32_t aoff = (uint32_t)((m0w + (q & 1) * 8 + r) * PITCH + (q >> 1) * 8) * 2;
    // B: tile q -> (q>>1)*8 n-rows, (q&1)*8 k-cols
    uint32_t boff = (uint32_t)((n0w + (q >> 1) * 8 + r) * PITCH + (q & 1) * 8) * 2;

    float d[2][8][4];
    #pragma unroll
    for (int i = 0; i < 2; i++)
        #pragma unroll
        for (int j = 0; j < 8; j++)
            #pragma unroll
            for (int c = 0; c < 4; c++) d[i][j][c] = 0.0f;

    for (int kc = 0; kc < kchunks; kc++) {
        // ---- stage A: fp32 -> split bf16 hi/lo, padded rows ----
        #pragma unroll
        for (int it = 0; it < 16; it++) {
            int flat = it * 256 + tid;               // 4096 float4
            int row = flat >> 5, col = (flat & 31) * 4;
            float4 v = *(const float4*)(A + (size_t)(brow + row) * K + kc * 128 + col);
            uint16_t h0,l0,h1,l1,h2,l2,h3,l3;
            split2(v.x, h0, l0); split2(v.y, h1, l1);
            split2(v.z, h2, l2); split2(v.w, h3, l3);
            uint32_t off = (uint32_t)(row * PITCH + col) * 2;
            *(uint32_t*)(smem + SM_AHI + off)     = (uint32_t)h0 | ((uint32_t)h1 << 16);
            *(uint32_t*)(smem + SM_AHI + off + 4) = (uint32_t)h2 | ((uint32_t)h3 << 16);
            *(uint32_t*)(smem + SM_ALO + off)     = (uint32_t)l0 | ((uint32_t)l1 << 16);
            *(uint32_t*)(smem + SM_ALO + off + 4) = (uint32_t)l2 | ((uint32_t)l3 << 16);
        }
        // ---- stage B: copy pre-split image into padded rows ----
        {
            const uint4* sh = (const uint4*)(img + (size_t)(ntile * kchunks + kc) * 32768);
            const uint4* sl = sh + 2048;             // lo half (16384 bf16)
            #pragma unroll
            for (int it = 0; it < 8; it++) {
                int j = it * 256 + tid;              // 2048 uint4
                int n = j >> 4, kq = j & 15;
                uint32_t off = (uint32_t)(n * PITCH + kq * 8) * 2;
                *(uint4*)(smem + SM_BHI + off) = sh[j];
                *(uint4*)(smem + SM_BLO + off) = sl[j];
            }
        }
        __syncthreads();

        #pragma unroll
        for (int ks = 0; ks < 8; ks++) {
            uint32_t ah[2][4], al[2][4];
            #pragma unroll
            for (int mt = 0; mt < 2; mt++) {
                uint32_t ao = aoff + mt * (16 * PITCH * 2) + ks * 32;
                ldm4(ah[mt], sb + SM_AHI + ao);
                ldm4(al[mt], sb + SM_ALO + ao);
            }
            #pragma unroll
            for (int nt = 0; nt < 4; nt++) {
                uint32_t bo = boff + nt * (16 * PITCH * 2) + ks * 32;
                uint32_t bh[4], bl[4];
                ldm4(bh, sb + SM_BHI + bo);
                ldm4(bl, sb + SM_BLO + bo);
                #pragma unroll
                for (int mt = 0; mt < 2; mt++) {
                    mma16816(d[mt][2*nt],   ah[mt], bh[0], bh[1]);
                    mma16816(d[mt][2*nt+1], ah[mt], bh[2], bh[3]);
                    mma16816(d[mt][2*nt],   ah[mt], bl[0], bl[1]);
                    mma16816(d[mt][2*nt+1], ah[mt], bl[2], bl[3]);
                    mma16816(d[mt][2*nt],   al[mt], bh[0], bh[1]);
                    mma16816(d[mt][2*nt+1], al[mt], bh[2], bh[3]);
                }
            }
        }
        __syncthreads();
    }

    // ---- epilogue ----
    int rq = lane >> 2, cq = lane & 3;
    #pragma unroll
    for (int mt = 0; mt < 2; mt++) {
        int row0 = brow + m0w + mt * 16 + rq;
        #pragma unroll
        for (int nt = 0; nt < 8; nt++) {
            int col = ntile * 128 + n0w + nt * 8 + cq * 2;
            *(float2*)(C + (size_t)row0 * ldc + col)       = make_float2(d[mt][nt][0], d[mt][nt][1]);
            *(float2*)(C + (size_t)(row0 + 8) * ldc + col) = make_float2(d[mt][nt][2], d[mt][nt][3]);
        }
    }
}

// ------------------------- GRU elementwise -----------------------------------
__global__ void gru_kernel(const float* __restrict__ hprev,
                           const float* __restrict__ bi_, const float* __restrict__ bh_,
                           int last) {
    int node = blockIdx.x;
    int t    = threadIdx.x;
    float hv = hprev[(size_t)node * Hh + t];
    if (g_ncnt[node] > 0) {
        size_t base = (size_t)node * 3 * Hh;
        float gr  = g_gi[base + t]          + bi_[t]          + g_gh[base + t]          + bh_[t];
        float gz  = g_gi[base + Hh + t]     + bi_[Hh + t]     + g_gh[base + Hh + t]     + bh_[Hh + t];
        float gin = g_gi[base + 2 * Hh + t] + bi_[2 * Hh + t];
        float ghn = g_gh[base + 2 * Hh + t] + bh_[2 * Hh + t];
        float r = sigm_f(gr);
        float z = sigm_f(gz);
        float n = tanh_f(fmaf(r, ghn, gin));
        hv = (1.0f - z) * n + z * hv;
    }
    g_h[(size_t)node * Hh + t] = hv;
    if (last) g_xr[(size_t)node * 2 * Hh + t] = hv;
}

// ------------------------- gated readout reduction ---------------------------
__global__ void readout_kernel(const float* __restrict__ bg, const float* __restrict__ bo,
                               float* __restrict__ out) {
    int b = blockIdx.x;
    int o = threadIdx.x;
    float acc = 0.0f;
    for (int i = 0; i < Nn; i++) {
        int node = b * Nn + i;
        if (g_ncnt[node] > 0) {
            float g = g_R[(size_t)node * 2 * NOUT + o]        + bg[o];
            float e = g_R[(size_t)node * 2 * NOUT + NOUT + o] + bo[o];
            acc = fmaf(sigm_f(g), e, acc);
        }
    }
    out[(size_t)b * NOUT + o] = acc;
}

// ------------------------- host orchestration --------------------------------
extern "C" void kernel_launch(void* const* d_in, const int* in_sizes, int n_in,
                              void* d_out, int out_size) {
    const float* nodes = (const float*)d_in[0];
    const float* edges = (const float*)d_in[1];
    const float* We    = (const float*)d_in[2];
    const float* Wn    = (const float*)d_in[3];
    const float* Wm    = (const float*)d_in[4];
    const float* Wi    = (const float*)d_in[5];
    const float* Wh    = (const float*)d_in[6];
    const float* bi_   = (const float*)d_in[7];
    const float* bh_   = (const float*)d_in[8];
    const float* Wg    = (const float*)d_in[9];
    const float* bg    = (const float*)d_in[10];
    const float* Wo    = (const float*)d_in[11];
    const float* bo    = (const float*)d_in[12];
    float* out = (float*)d_out;

    float *p_h, *p_proj, *p_msg, *p_gi, *p_gh, *p_xr, *p_R;
    __nv_bfloat16 *p_wpr, *p_wih, *p_wro;
    cudaGetSymbolAddress((void**)&p_h,    g_h);
    cudaGetSymbolAddress((void**)&p_proj, g_proj);
    cudaGetSymbolAddress((void**)&p_msg,  g_msg);
    cudaGetSymbolAddress((void**)&p_gi,   g_gi);
    cudaGetSymbolAddress((void**)&p_gh,   g_gh);
    cudaGetSymbolAddress((void**)&p_xr,   g_xr);
    cudaGetSymbolAddress((void**)&p_R,    g_R);
    cudaGetSymbolAddress((void**)&p_wpr,  g_Wpr_img);
    cudaGetSymbolAddress((void**)&p_wih,  g_Wih_img);
    cudaGetSymbolAddress((void**)&p_wro,  g_Wro_img);

    cudaFuncSetAttribute(gemm_tc, cudaFuncAttributeMaxDynamicSharedMemorySize, GEMM_SMEM);

    // prep
    prep_xr <<<(NODES * Hh + 255) / 256, 256>>>(nodes);
    prep_wpr<<<(2 * 16384) / 256, 256>>>(Wn, Wm);
    prep_wih<<<(6 * 16384) / 256, 256>>>(Wi, Wh);
    prep_wro<<<(4 * 16384) / 256, 256>>>(Wg, Wo);
    prep_graph<<<NODES, 64>>>(edges);

    const int ROWB = NODES / 128;  // 160
    // initial projection: proj = nodes @ [Wn|Wm]
    gemm_tc<<<dim3(2, ROWB, 1), 256, GEMM_SMEM>>>(
        nodes, nodes, p_proj, p_proj, p_wpr, p_wpr, 128, 256);

    const float* hsrc = nodes;
    for (int p = 0; p < NPASS; p++) {
        attn_kernel<<<NODES, 128>>>(We);
        gemm_tc<<<dim3(3, ROWB, 2), 256, GEMM_SMEM>>>(
            p_msg, hsrc, p_gi, p_gh, p_wih, p_wih + (size_t)3 * 32768, 128, 384);
        gru_kernel<<<NODES, 128>>>(hsrc, bi_, bh_, (p == NPASS - 1) ? 1 : 0);
        hsrc = p_h;
        if (p < NPASS - 1) {
            gemm_tc<<<dim3(2, ROWB, 1), 256, GEMM_SMEM>>>(
                hsrc, hsrc, p_proj, p_proj, p_wpr, p_wpr, 128, 256);
        }
    }

    // readout: R = [h|nodes] @ [Wg|Wo]   (K = 256 -> kchunks = 2)
    gemm_tc<<<dim3(2, ROWB, 1), 256, GEMM_SMEM>>>(
        p_xr, p_xr, p_R, p_R, p_wro, p_wro, 256, 256);
    readout_kernel<<<Bb, 128>>>(bg, bo, out);
    (void)in_sizes; (void)n_in; (void)out_size;
}

// round 5
// speedup vs baseline: 1.8132x; 1.1651x over previous
#include <cuda_runtime.h>
#include <cuda_bf16.h>
#include <stdint.h>

#define Bb    512
#define Nn    40
#define Hh    128
#define FEe   16
#define Mm    128
#define NPASS 3
#define NOUT  128
#define NODES (Bb * Nn)   // 20480

// ------------------------- device scratch ------------------------------------
__device__ float g_h   [NODES * Hh];
__device__ float g_proj[NODES * 2 * Mm];
__device__ float g_msg [NODES * Mm];
__device__ float g_gi  [NODES * 3 * Hh];
__device__ float g_gh  [NODES * 3 * Hh];
__device__ float g_xr  [NODES * 2 * Hh];
__device__ float g_R   [NODES * 2 * NOUT];
__device__ float g_ec  [NODES * Nn * FEe];
__device__ int   g_nbr [NODES * Nn];
__device__ int   g_ncnt[NODES];
// pre-split, pre-transposed bf16 weight images, chunked by K=64.
// chunk = 16384 bf16: [hi: [128 n][64 k]] [lo: same]. chunk id = ntile*KCH + kc.
__device__ __nv_bfloat16 g_Wpr_img[2 * 2 * 16384];      // tiles=2, KCH=2
__device__ __nv_bfloat16 g_Wih_img[2 * 3 * 2 * 16384];  // z=2, tiles=3, KCH=2
__device__ __nv_bfloat16 g_Wro_img[2 * 4 * 16384];      // tiles=2, KCH=4

// ------------------------- helpers -------------------------------------------
__device__ __forceinline__ uint32_t smem_u32(const void* p) {
    uint32_t a;
    asm("{ .reg .u64 t; cvta.to.shared.u64 t, %1; cvt.u32.u64 %0, t; }" : "=r"(a) : "l"(p));
    return a;
}
__device__ __forceinline__ void split2(float x, uint16_t& h, uint16_t& l) {
    __nv_bfloat16 hb = __float2bfloat16_rn(x);
    __nv_bfloat16 lb = __float2bfloat16_rn(x - __bfloat162float(hb));
    h = __bfloat16_as_ushort(hb); l = __bfloat16_as_ushort(lb);
}
__device__ __forceinline__ float tanh_f(float x) {         // accurate (GRU)
    float e = __expf(2.0f * x);
    return 1.0f - __fdividef(2.0f, e + 1.0f);
}
__device__ __forceinline__ float tanh_hw(float x) {        // HW approx (attention)
    float y;
    asm("tanh.approx.f32 %0, %1;" : "=f"(y) : "f"(x));
    return y;
}
__device__ __forceinline__ float sigm_f(float x) {
    return __fdividef(1.0f, 1.0f + __expf(-x));
}
__device__ __forceinline__ void ldm4(uint32_t* r, uint32_t addr) {
    asm volatile("ldmatrix.sync.aligned.m8n8.x4.shared.b16 {%0,%1,%2,%3}, [%4];"
                 : "=r"(r[0]), "=r"(r[1]), "=r"(r[2]), "=r"(r[3]) : "r"(addr));
}
__device__ __forceinline__ void mma16816(float* d, const uint32_t* a, uint32_t b0, uint32_t b1) {
    asm volatile(
        "mma.sync.aligned.m16n8k16.row.col.f32.bf16.bf16.f32 "
        "{%0,%1,%2,%3}, {%4,%5,%6,%7}, {%8,%9}, {%0,%1,%2,%3};\n"
        : "+f"(d[0]), "+f"(d[1]), "+f"(d[2]), "+f"(d[3])
        : "r"(a[0]), "r"(a[1]), "r"(a[2]), "r"(a[3]), "r"(b0), "r"(b1));
}
__device__ __forceinline__ void cp_async16(uint32_t dst, const void* src) {
    asm volatile("cp.async.cg.shared.global [%0], [%1], 16;" :: "r"(dst), "l"(src));
}

// ------------------------- prep kernels --------------------------------------
__global__ void prep_xr(const float* __restrict__ nodes) {
    int idx = blockIdx.x * blockDim.x + threadIdx.x;
    if (idx < NODES * Hh) {
        int node = idx >> 7, c = idx & 127;
        g_xr[node * 2 * Hh + Hh + c] = nodes[idx];
    }
}
// single merged weight-prep: writes all three chunked images
__global__ void prep_w(const float* __restrict__ Wn, const float* __restrict__ Wm,
                       const float* __restrict__ Wi, const float* __restrict__ Wh,
                       const float* __restrict__ Wg, const float* __restrict__ Wo) {
    int idx = blockIdx.x * blockDim.x + threadIdx.x;   // 196608 total
    uint16_t hv, lv;
    if (idx < 32768) {                                  // Wpr: 2 tiles x 2 kc x 8192
        int e = idx;
        int tile = e >> 14, r = e & 16383;
        int kc = r >> 13, f = r & 8191;
        int n = f >> 6, k64 = f & 63;
        int k = kc * 64 + k64;
        float x = tile ? Wm[k * Mm + n] : Wn[k * Mm + n];
        split2(x, hv, lv);
        uint16_t* base = (uint16_t*)(g_Wpr_img + (size_t)(tile * 2 + kc) * 16384);
        base[n * 64 + k64] = hv;
        base[8192 + n * 64 + k64] = lv;
    } else if (idx < 131072) {                          // Wih: 2 z x 3 tiles x 2 kc x 8192
        int e = idx - 32768;
        int z = e / 49152, r = e % 49152;
        int tile = r / 16384, rr = r % 16384;
        int kc = rr >> 13, f = rr & 8191;
        int n = f >> 6, k64 = f & 63;
        int k = kc * 64 + k64;
        const float* W = z ? Wh : Wi;
        float x = W[k * 384 + tile * 128 + n];
        split2(x, hv, lv);
        uint16_t* base = (uint16_t*)(g_Wih_img + (size_t)((z * 3 + tile) * 2 + kc) * 16384);
        base[n * 64 + k64] = hv;
        base[8192 + n * 64 + k64] = lv;
    } else if (idx < 196608) {                          // Wro: 2 tiles x 4 kc x 8192
        int e = idx - 131072;
        int tile = e >> 15, r = e & 32767;
        int kc = r >> 13, f = r & 8191;
        int n = f >> 6, k64 = f & 63;
        int k = kc * 64 + k64;
        float x = tile ? Wo[k * NOUT + n] : Wg[k * NOUT + n];
        split2(x, hv, lv);
        uint16_t* base = (uint16_t*)(g_Wro_img + (size_t)(tile * 4 + kc) * 16384);
        base[n * 64 + k64] = hv;
        base[8192 + n * 64 + k64] = lv;
    }
}

__global__ void prep_graph(const float* __restrict__ edges) {
    int bi = blockIdx.x;
    const float* erow = edges + (size_t)bi * (Nn * FEe);
    __shared__ float ssum[Nn];
    __shared__ int   slist[Nn];
    __shared__ int   snc;
    int t = threadIdx.x;                      // 64 threads
    if (t < Nn) {
        const float4* p = (const float4*)(erow + t * FEe);
        float s = 0.f;
        #pragma unroll
        for (int q = 0; q < 4; q++) { float4 v = p[q]; s += v.x + v.y + v.z + v.w; }
        ssum[t] = s;
    }
    __syncthreads();
    if (t == 0) {
        int c = 0;
        for (int j = 0; j < Nn; j++) if (ssum[j] > 0.f) slist[c++] = j;
        snc = c; g_ncnt[bi] = c;
    }
    __syncthreads();
    int nc = snc;
    if (t < nc) g_nbr[bi * Nn + t] = slist[t];
    float4* dst = (float4*)(g_ec + (size_t)bi * Nn * FEe);
    for (int idx = t; idx < nc * 4; idx += blockDim.x) {
        int k = idx >> 2, q = idx & 3;
        dst[idx] = ((const float4*)(erow + slist[k] * FEe))[q];
    }
}

// ------------------------- fused attention + messages ------------------------
__global__ void attn_kernel(const float* __restrict__ We) {
    int bi = blockIdx.x;
    int m  = threadIdx.x;
    int b  = bi / Nn;
    int nc = g_ncnt[bi];
    if (nc == 0) { g_msg[bi * Mm + m] = 0.0f; return; }

    __shared__ __align__(16) float ef[Nn][FEe];
    __shared__ int jl[Nn];
    const float4* src = (const float4*)(g_ec + (size_t)bi * Nn * FEe);
    float4* efv = (float4*)&ef[0][0];
    for (int idx = m; idx < nc * 4; idx += blockDim.x) efv[idx] = src[idx];
    if (m < nc) jl[m] = g_nbr[bi * Nn + m];
    __syncthreads();

    float we[FEe];
    #pragma unroll
    for (int f = 0; f < FEe; f++) we[f] = We[f * Mm + m];

    const float* projb = g_proj + (size_t)b * Nn * 2 * Mm;
    float s = 0.0f, acc = 0.0f;
    #pragma unroll 2
    for (int k = 0; k < nc; k++) {
        int j = jl[k];
        float nb = __ldg(projb + j * 2 * Mm + m);
        float em = __ldg(projb + j * 2 * Mm + Mm + m);
        float x = nb;
        #pragma unroll
        for (int f = 0; f < FEe; f++) x = fmaf(ef[k][f], we[f], x);
        float p = __expf(tanh_hw(x));
        s += p;
        acc = fmaf(p, em, acc);
    }
    g_msg[bi * Mm + m] = __fdividef(acc, s);
}

// ------------------------- HMMA split-bf16 GEMM -------------------------------
// C tile (128M x 128N) = A[., K] @ W(chunked images), fp32 accumulate.
// K processed in 64-wide chunks; smem 72KB -> 2 blocks/SM; B staged via cp.async.
// 256 thr, warp grid 4(M) x 2(N), per-warp 32x64, mma.m16n8k16 bf16.
// smem pitch 72 bf16 (144B): row stride = 36 words ≡ 4 (mod 32) -> ldmatrix
// conflict-free, 16B-aligned.
#define PITCH 72
#define TILEB (128 * PITCH * 2)          // 18432 bytes per tile
#define SM_AHI 0
#define SM_ALO (TILEB)
#define SM_BHI (2 * TILEB)
#define SM_BLO (3 * TILEB)
#define GEMM_SMEM (4 * TILEB)            // 73728

__global__ __launch_bounds__(256, 2) void gemm_tc(
    const float* A0, const float* A1, float* C0, float* C1,
    const __nv_bfloat16* img0, const __nv_bfloat16* img1,
    int K, int ldc)
{
    extern __shared__ char smem[];
    const float* A = blockIdx.z ? A1 : A0;
    float*       C = blockIdx.z ? C1 : C0;
    const __nv_bfloat16* img = blockIdx.z ? img1 : img0;

    uint32_t sb = smem_u32(smem);
    int tid = threadIdx.x, wid = tid >> 5, lane = tid & 31;
    int brow = blockIdx.y * 128;
    int ntile = blockIdx.x;
    int kchunks = K >> 6;

    int m0w = (wid & 3) * 32;        // warp M offset
    int n0w = (wid >> 2) * 64;       // warp N offset

    int q = lane >> 3, r = lane & 7;
    uint32_t aoff = (uint32_t)((m0w + (q & 1) * 8 + r) * PITCH + (q >> 1) * 8) * 2;
    uint32_t boff = (uint32_t)((n0w + (q >> 1) * 8 + r) * PITCH + (q & 1) * 8) * 2;

    float d[2][8][4];
    #pragma unroll
    for (int i = 0; i < 2; i++)
        #pragma unroll
        for (int j = 0; j < 8; j++)
            #pragma unroll
            for (int c = 0; c < 4; c++) d[i][j][c] = 0.0f;

    // B staging dest offsets (per-thread, 4 rows apart in j)
    for (int kc = 0; kc < kchunks; kc++) {
        // ---- B: cp.async pre-split image chunk into padded smem ----
        {
            const uint4* sh = (const uint4*)(img + (size_t)(ntile * kchunks + kc) * 16384);
            const uint4* sl = sh + 1024;
            #pragma unroll
            for (int it = 0; it < 4; it++) {
                int j = it * 256 + tid;              // 1024 uint4 per tile
                int n = j >> 3, kq = j & 7;
                uint32_t off = (uint32_t)(n * PITCH + kq * 8) * 2;
                cp_async16(sb + SM_BHI + off, sh + j);
                cp_async16(sb + SM_BLO + off, sl + j);
            }
            asm volatile("cp.async.commit_group;" ::: "memory");
        }
        // ---- A: fp32 -> split bf16 hi/lo into padded smem ----
        #pragma unroll
        for (int it = 0; it < 8; it++) {
            int flat = it * 256 + tid;               // 2048 float4
            int row = flat >> 4, col = (flat & 15) * 4;
            float4 v = *(const float4*)(A + (size_t)(brow + row) * K + kc * 64 + col);
            uint16_t h0,l0,h1,l1,h2,l2,h3,l3;
            split2(v.x, h0, l0); split2(v.y, h1, l1);
            split2(v.z, h2, l2); split2(v.w, h3, l3);
            uint32_t off = (uint32_t)(row * PITCH + col) * 2;
            *(uint32_t*)(smem + SM_AHI + off)     = (uint32_t)h0 | ((uint32_t)h1 << 16);
            *(uint32_t*)(smem + SM_AHI + off + 4) = (uint32_t)h2 | ((uint32_t)h3 << 16);
            *(uint32_t*)(smem + SM_ALO + off)     = (uint32_t)l0 | ((uint32_t)l1 << 16);
            *(uint32_t*)(smem + SM_ALO + off + 4) = (uint32_t)l2 | ((uint32_t)l3 << 16);
        }
        asm volatile("cp.async.wait_all;" ::: "memory");
        __syncthreads();

        #pragma unroll
        for (int ks = 0; ks < 4; ks++) {
            uint32_t ah[2][4], al[2][4];
            #pragma unroll
            for (int mt = 0; mt < 2; mt++) {
                uint32_t ao = aoff + mt * (16 * PITCH * 2) + ks * 32;
                ldm4(ah[mt], sb + SM_AHI + ao);
                ldm4(al[mt], sb + SM_ALO + ao);
            }
            #pragma unroll
            for (int nt = 0; nt < 4; nt++) {
                uint32_t bo = boff + nt * (16 * PITCH * 2) + ks * 32;
                uint32_t bh[4], bl[4];
                ldm4(bh, sb + SM_BHI + bo);
                ldm4(bl, sb + SM_BLO + bo);
                #pragma unroll
                for (int mt = 0; mt < 2; mt++) {
                    mma16816(d[mt][2*nt],   ah[mt], bh[0], bh[1]);
                    mma16816(d[mt][2*nt+1], ah[mt], bh[2], bh[3]);
                    mma16816(d[mt][2*nt],   ah[mt], bl[0], bl[1]);
                    mma16816(d[mt][2*nt+1], ah[mt], bl[2], bl[3]);
                    mma16816(d[mt][2*nt],   al[mt], bh[0], bh[1]);
                    mma16816(d[mt][2*nt+1], al[mt], bh[2], bh[3]);
                }
            }
        }
        __syncthreads();
    }

    // ---- epilogue ----
    int rq = lane >> 2, cq = lane & 3;
    #pragma unroll
    for (int mt = 0; mt < 2; mt++) {
        int row0 = brow + m0w + mt * 16 + rq;
        #pragma unroll
        for (int nt = 0; nt < 8; nt++) {
            int col = ntile * 128 + n0w + nt * 8 + cq * 2;
            *(float2*)(C + (size_t)row0 * ldc + col)       = make_float2(d[mt][nt][0], d[mt][nt][1]);
            *(float2*)(C + (size_t)(row0 + 8) * ldc + col) = make_float2(d[mt][nt][2], d[mt][nt][3]);
        }
    }
}

// ------------------------- GRU elementwise -----------------------------------
__global__ void gru_kernel(const float* __restrict__ hprev,
                           const float* __restrict__ bi_, const float* __restrict__ bh_,
                           int last) {
    int node = blockIdx.x;
    int t    = threadIdx.x;
    float hv = hprev[(size_t)node * Hh + t];
    if (g_ncnt[node] > 0) {
        size_t base = (size_t)node * 3 * Hh;
        float gr  = g_gi[base + t]          + bi_[t]          + g_gh[base + t]          + bh_[t];
        float gz  = g_gi[base + Hh + t]     + bi_[Hh + t]     + g_gh[base + Hh + t]     + bh_[Hh + t];
        float gin = g_gi[base + 2 * Hh + t] + bi_[2 * Hh + t];
        float ghn = g_gh[base + 2 * Hh + t] + bh_[2 * Hh + t];
        float r = sigm_f(gr);
        float z = sigm_f(gz);
        float n = tanh_f(fmaf(r, ghn, gin));
        hv = (1.0f - z) * n + z * hv;
    }
    g_h[(size_t)node * Hh + t] = hv;
    if (last) g_xr[(size_t)node * 2 * Hh + t] = hv;
}

// ------------------------- gated readout reduction ---------------------------
__global__ void readout_kernel(const float* __restrict__ bg, const float* __restrict__ bo,
                               float* __restrict__ out) {
    int b = blockIdx.x;
    int o = threadIdx.x;
    float acc = 0.0f;
    for (int i = 0; i < Nn; i++) {
        int node = b * Nn + i;
        if (g_ncnt[node] > 0) {
            float g = g_R[(size_t)node * 2 * NOUT + o]        + bg[o];
            float e = g_R[(size_t)node * 2 * NOUT + NOUT + o] + bo[o];
            acc = fmaf(sigm_f(g), e, acc);
        }
    }
    out[(size_t)b * NOUT + o] = acc;
}

// ------------------------- host orchestration --------------------------------
extern "C" void kernel_launch(void* const* d_in, const int* in_sizes, int n_in,
                              void* d_out, int out_size) {
    const float* nodes = (const float*)d_in[0];
    const float* edges = (const float*)d_in[1];
    const float* We    = (const float*)d_in[2];
    const float* Wn    = (const float*)d_in[3];
    const float* Wm    = (const float*)d_in[4];
    const float* Wi    = (const float*)d_in[5];
    const float* Wh    = (const float*)d_in[6];
    const float* bi_   = (const float*)d_in[7];
    const float* bh_   = (const float*)d_in[8];
    const float* Wg    = (const float*)d_in[9];
    const float* bg    = (const float*)d_in[10];
    const float* Wo    = (const float*)d_in[11];
    const float* bo    = (const float*)d_in[12];
    float* out = (float*)d_out;

    float *p_h, *p_proj, *p_msg, *p_gi, *p_gh, *p_xr, *p_R;
    __nv_bfloat16 *p_wpr, *p_wih, *p_wro;
    cudaGetSymbolAddress((void**)&p_h,    g_h);
    cudaGetSymbolAddress((void**)&p_proj, g_proj);
    cudaGetSymbolAddress((void**)&p_msg,  g_msg);
    cudaGetSymbolAddress((void**)&p_gi,   g_gi);
    cudaGetSymbolAddress((void**)&p_gh,   g_gh);
    cudaGetSymbolAddress((void**)&p_xr,   g_xr);
    cudaGetSymbolAddress((void**)&p_R,    g_R);
    cudaGetSymbolAddress((void**)&p_wpr,  g_Wpr_img);
    cudaGetSymbolAddress((void**)&p_wih,  g_Wih_img);
    cudaGetSymbolAddress((void**)&p_wro,  g_Wro_img);

    cudaFuncSetAttribute(gemm_tc, cudaFuncAttributeMaxDynamicSharedMemorySize, GEMM_SMEM);

    // prep
    prep_xr <<<(NODES * Hh + 255) / 256, 256>>>(nodes);
    prep_w  <<<196608 / 256, 256>>>(Wn, Wm, Wi, Wh, Wg, Wo);
    prep_graph<<<NODES, 64>>>(edges);

    const int ROWB = NODES / 128;  // 160
    // initial projection: proj = nodes @ [Wn|Wm]
    gemm_tc<<<dim3(2, ROWB, 1), 256, GEMM_SMEM>>>(
        nodes, nodes, p_proj, p_proj, p_wpr, p_wpr, 128, 256);

    const float* hsrc = nodes;
    for (int p = 0; p < NPASS; p++) {
        attn_kernel<<<NODES, 128>>>(We);
        gemm_tc<<<dim3(3, ROWB, 2), 256, GEMM_SMEM>>>(
            p_msg, hsrc, p_gi, p_gh, p_wih, p_wih + (size_t)6 * 16384, 128, 384);
        gru_kernel<<<NODES, 128>>>(hsrc, bi_, bh_, (p == NPASS - 1) ? 1 : 0);
        hsrc = p_h;
        if (p < NPASS - 1) {
            gemm_tc<<<dim3(2, ROWB, 1), 256, GEMM_SMEM>>>(
                hsrc, hsrc, p_proj, p_proj, p_wpr, p_wpr, 128, 256);
        }
    }

    // readout: R = [h|nodes] @ [Wg|Wo]   (K = 256 -> 4 chunks)
    gemm_tc<<<dim3(2, ROWB, 1), 256, GEMM_SMEM>>>(
        p_xr, p_xr, p_R, p_R, p_wro, p_wro, 256, 256);
    readout_kernel<<<Bb, 128>>>(bg, bo, out);
    (void)in_sizes; (void)n_in; (void)out_size;
}

// round 6
// speedup vs baseline: 1.9028x; 1.0494x over previous
#include <cuda_runtime.h>
#include <cuda_bf16.h>
#include <stdint.h>

#define Bb    512
#define Nn    40
#define Hh    128
#define FEe   16
#define Mm    128
#define NPASS 3
#define NOUT  128
#define NODES (Bb * Nn)   // 20480

// ------------------------- device scratch ------------------------------------
__device__ float g_h   [NODES * Hh];          // fp32 carried hidden state
__device__ float g_proj[NODES * 2 * Mm];
__device__ float g_gi  [NODES * 3 * Hh];
__device__ float g_gh  [NODES * 3 * Hh];
__device__ float g_R   [NODES * 2 * NOUT];
__device__ float g_ec  [NODES * Nn * FEe];
__device__ int   g_nbr [NODES * Nn];
__device__ int   g_ncnt[NODES];
// pre-split bf16 A operands (row-major [rows][K])
__device__ __nv_bfloat16 g_h_hi  [NODES * Hh];
__device__ __nv_bfloat16 g_h_lo  [NODES * Hh];
__device__ __nv_bfloat16 g_msg_hi[NODES * Mm];
__device__ __nv_bfloat16 g_msg_lo[NODES * Mm];
__device__ __nv_bfloat16 g_xr_hi [NODES * 2 * Hh];
__device__ __nv_bfloat16 g_xr_lo [NODES * 2 * Hh];
// pre-split, pre-transposed bf16 weight images, chunked (64n x 64k).
// chunk = 8192 bf16: [hi: n(64)*64 + k] [lo: +4096]. chunk id = ntile*KCH + kc.
__device__ __nv_bfloat16 g_Wpr_img[8 * 8192];        // 4 tiles x 2 kc
__device__ __nv_bfloat16 g_Wih_img[2 * 12 * 8192];   // z2 x (6 tiles x 2 kc)
__device__ __nv_bfloat16 g_Wro_img[16 * 8192];       // 4 tiles x 4 kc

// ------------------------- helpers -------------------------------------------
__device__ __forceinline__ uint32_t smem_u32(const void* p) {
    uint32_t a;
    asm("{ .reg .u64 t; cvta.to.shared.u64 t, %1; cvt.u32.u64 %0, t; }" : "=r"(a) : "l"(p));
    return a;
}
__device__ __forceinline__ void split2(float x, uint16_t& h, uint16_t& l) {
    __nv_bfloat16 hb = __float2bfloat16_rn(x);
    __nv_bfloat16 lb = __float2bfloat16_rn(x - __bfloat162float(hb));
    h = __bfloat16_as_ushort(hb); l = __bfloat16_as_ushort(lb);
}
__device__ __forceinline__ float tanh_f(float x) {         // accurate (GRU)
    float e = __expf(2.0f * x);
    return 1.0f - __fdividef(2.0f, e + 1.0f);
}
__device__ __forceinline__ float tanh_hw(float x) {        // HW approx (attention)
    float y;
    asm("tanh.approx.f32 %0, %1;" : "=f"(y) : "f"(x));
    return y;
}
__device__ __forceinline__ float sigm_f(float x) {
    return __fdividef(1.0f, 1.0f + __expf(-x));
}
__device__ __forceinline__ void ldm4(uint32_t* r, uint32_t addr) {
    asm volatile("ldmatrix.sync.aligned.m8n8.x4.shared.b16 {%0,%1,%2,%3}, [%4];"
                 : "=r"(r[0]), "=r"(r[1]), "=r"(r[2]), "=r"(r[3]) : "r"(addr));
}
__device__ __forceinline__ void mma16816(float* d, const uint32_t* a, uint32_t b0, uint32_t b1) {
    asm volatile(
        "mma.sync.aligned.m16n8k16.row.col.f32.bf16.bf16.f32 "
        "{%0,%1,%2,%3}, {%4,%5,%6,%7}, {%8,%9}, {%0,%1,%2,%3};\n"
        : "+f"(d[0]), "+f"(d[1]), "+f"(d[2]), "+f"(d[3])
        : "r"(a[0]), "r"(a[1]), "r"(a[2]), "r"(a[3]), "r"(b0), "r"(b1));
}
__device__ __forceinline__ void cp_async16(uint32_t dst, const void* src) {
    asm volatile("cp.async.cg.shared.global [%0], [%1], 16;" :: "r"(dst), "l"(src));
}

// ------------------------- prep kernels --------------------------------------
__global__ void prep_xr(const float* __restrict__ nodes) {
    int idx = blockIdx.x * blockDim.x + threadIdx.x;
    if (idx < NODES * Hh) {
        int node = idx >> 7, c = idx & 127;
        float x = nodes[idx];
        uint16_t h, l; split2(x, h, l);
        g_h_hi[idx] = __ushort_as_bfloat16(h);            // initial h = nodes
        g_h_lo[idx] = __ushort_as_bfloat16(l);
        g_xr_hi[node * 256 + 128 + c] = __ushort_as_bfloat16(h);
        g_xr_lo[node * 256 + 128 + c] = __ushort_as_bfloat16(l);
    }
}
// merged weight prep: all chunked images (196608 threads)
__global__ void prep_w(const float* __restrict__ Wn, const float* __restrict__ Wm,
                       const float* __restrict__ Wi, const float* __restrict__ Wh,
                       const float* __restrict__ Wg, const float* __restrict__ Wo) {
    int idx = blockIdx.x * blockDim.x + threadIdx.x;
    uint16_t hv, lv;
    if (idx < 32768) {                                  // Wpr: chunks 0..7
        int chunk = idx >> 12, f = idx & 4095;
        int n = f >> 6, k64 = f & 63;
        int tile = chunk >> 1, kc = chunk & 1;
        int k = kc * 64 + k64, ng = tile * 64 + n;
        float x = (ng < 128) ? Wn[k * 128 + ng] : Wm[k * 128 + ng - 128];
        split2(x, hv, lv);
        __nv_bfloat16* base = g_Wpr_img + (size_t)chunk * 8192;
        base[n * 64 + k64]        = __ushort_as_bfloat16(hv);
        base[4096 + n * 64 + k64] = __ushort_as_bfloat16(lv);
    } else if (idx < 131072) {                          // Wih
        int e = idx - 32768;
        int z = e / 49152, r = e % 49152;
        int chunk = r >> 12, f = r & 4095;
        int n = f >> 6, k64 = f & 63;
        int tile = chunk >> 1, kc = chunk & 1;
        int k = kc * 64 + k64, ng = tile * 64 + n;
        const float* W = z ? Wh : Wi;
        float x = W[k * 384 + ng];
        split2(x, hv, lv);
        __nv_bfloat16* base = g_Wih_img + (size_t)(z * 12 + chunk) * 8192;
        base[n * 64 + k64]        = __ushort_as_bfloat16(hv);
        base[4096 + n * 64 + k64] = __ushort_as_bfloat16(lv);
    } else if (idx < 196608) {                          // Wro
        int e = idx - 131072;
        int chunk = e >> 12, f = e & 4095;
        int n = f >> 6, k64 = f & 63;
        int tile = chunk >> 2, kc = chunk & 3;
        int k = kc * 64 + k64, ng = tile * 64 + n;
        float x = (ng < 128) ? Wg[k * 128 + ng] : Wo[k * 128 + ng - 128];
        split2(x, hv, lv);
        __nv_bfloat16* base = g_Wro_img + (size_t)chunk * 8192;
        base[n * 64 + k64]        = __ushort_as_bfloat16(hv);
        base[4096 + n * 64 + k64] = __ushort_as_bfloat16(lv);
    }
}

__global__ void prep_graph(const float* __restrict__ edges) {
    int bi = blockIdx.x;
    const float* erow = edges + (size_t)bi * (Nn * FEe);
    __shared__ float ssum[Nn];
    __shared__ int   slist[Nn];
    __shared__ int   snc;
    int t = threadIdx.x;                      // 64 threads
    if (t < Nn) {
        const float4* p = (const float4*)(erow + t * FEe);
        float s = 0.f;
        #pragma unroll
        for (int q = 0; q < 4; q++) { float4 v = p[q]; s += v.x + v.y + v.z + v.w; }
        ssum[t] = s;
    }
    __syncthreads();
    if (t == 0) {
        int c = 0;
        for (int j = 0; j < Nn; j++) if (ssum[j] > 0.f) slist[c++] = j;
        snc = c; g_ncnt[bi] = c;
    }
    __syncthreads();
    int nc = snc;
    if (t < nc) g_nbr[bi * Nn + t] = slist[t];
    float4* dst = (float4*)(g_ec + (size_t)bi * Nn * FEe);
    for (int idx = t; idx < nc * 4; idx += blockDim.x) {
        int k = idx >> 2, q = idx & 3;
        dst[idx] = ((const float4*)(erow + slist[k] * FEe))[q];
    }
}

// ------------------------- fused attention + messages ------------------------
__global__ void attn_kernel(const float* __restrict__ We) {
    int bi = blockIdx.x;
    int m  = threadIdx.x;
    int b  = bi / Nn;
    int nc = g_ncnt[bi];
    if (nc == 0) {
        g_msg_hi[bi * Mm + m] = __ushort_as_bfloat16(0);
        g_msg_lo[bi * Mm + m] = __ushort_as_bfloat16(0);
        return;
    }

    __shared__ __align__(16) float ef[Nn][FEe];
    __shared__ int jl[Nn];
    const float4* src = (const float4*)(g_ec + (size_t)bi * Nn * FEe);
    float4* efv = (float4*)&ef[0][0];
    for (int idx = m; idx < nc * 4; idx += blockDim.x) efv[idx] = src[idx];
    if (m < nc) jl[m] = g_nbr[bi * Nn + m];
    __syncthreads();

    float we[FEe];
    #pragma unroll
    for (int f = 0; f < FEe; f++) we[f] = We[f * Mm + m];

    const float* projb = g_proj + (size_t)b * Nn * 2 * Mm;
    float s = 0.0f, acc = 0.0f;
    #pragma unroll 2
    for (int k = 0; k < nc; k++) {
        int j = jl[k];
        float nb = __ldg(projb + j * 2 * Mm + m);
        float em = __ldg(projb + j * 2 * Mm + Mm + m);
        float x = nb;
        #pragma unroll
        for (int f = 0; f < FEe; f++) x = fmaf(ef[k][f], we[f], x);
        float p = __expf(tanh_hw(x));
        s += p;
        acc = fmaf(p, em, acc);
    }
    float v = __fdividef(acc, s);
    uint16_t h, l; split2(v, h, l);
    g_msg_hi[bi * Mm + m] = __ushort_as_bfloat16(h);
    g_msg_lo[bi * Mm + m] = __ushort_as_bfloat16(l);
}

// ------------------------- HMMA split-bf16 GEMM (pipelined) -------------------
// C tile (128M x 64N) = A(hi/lo bf16 images) @ W(chunked images), fp32 accum.
// K in 64-chunks, FULL double-buffered cp.async staging (A and B).
// 256 thr, warp grid 4(M) x 2(N), per-warp 32x32. Pitch 72 bf16 -> ldmatrix
// conflict-free.  smem/block 110592 -> 2 blocks/SM.
#define PITCH  72
#define ROWB2  144                       // bytes per smem row
#define ABUF   18432                     // 128 * 144
#define BBUF   9216                      // 64 * 144
#define STAGE  (2 * ABUF + 2 * BBUF)     // 55296
#define GEMM_SMEM (2 * STAGE)            // 110592

__global__ __launch_bounds__(256, 2) void gemm_tc(
    const __nv_bfloat16* Ah0, const __nv_bfloat16* Al0,
    const __nv_bfloat16* Ah1, const __nv_bfloat16* Al1,
    float* C0, float* C1,
    const __nv_bfloat16* img0, const __nv_bfloat16* img1,
    int K, int ldc)
{
    extern __shared__ char smem[];
    const __nv_bfloat16* Ahi = blockIdx.z ? Ah1 : Ah0;
    const __nv_bfloat16* Alo = blockIdx.z ? Al1 : Al0;
    float*               C   = blockIdx.z ? C1  : C0;
    const __nv_bfloat16* img = blockIdx.z ? img1 : img0;

    uint32_t sb = smem_u32(smem);
    int tid = threadIdx.x, wid = tid >> 5, lane = tid & 31;
    int brow = blockIdx.y * 128;
    int ntile = blockIdx.x;
    int nk = K >> 6;
    int K8 = K >> 3;                      // row stride in uint4

    const uint4* pAh = (const uint4*)(Ahi + (size_t)brow * K);
    const uint4* pAl = (const uint4*)(Alo + (size_t)brow * K);

    // ---- stage issue lambda-ish macro ----
    #define STAGE_CHUNK(kc) do {                                               \
        int _kc = (kc);                                                        \
        uint32_t _base = sb + (uint32_t)(_kc & 1) * STAGE;                     \
        int _kq4 = _kc * 8; /* uint4 offset of chunk in A row */               \
        _Pragma("unroll")                                                      \
        for (int _it = 0; _it < 4; _it++) {                                    \
            int _j = _it * 256 + tid;                                          \
            int _row = _j >> 3, _kq = _j & 7;                                  \
            uint32_t _d = _base + (uint32_t)(_row * ROWB2 + _kq * 16);         \
            cp_async16(_d,        pAh + (size_t)_row * K8 + _kq4 + _kq);       \
            cp_async16(_d + ABUF, pAl + (size_t)_row * K8 + _kq4 + _kq);       \
        }                                                                      \
        const uint4* _pB = (const uint4*)(img + (size_t)(ntile * nk + _kc) * 8192); \
        _Pragma("unroll")                                                      \
        for (int _it = 0; _it < 2; _it++) {                                    \
            int _j = _it * 256 + tid;                                          \
            int _n = _j >> 3, _kq = _j & 7;                                    \
            uint32_t _d = _base + 2 * ABUF + (uint32_t)(_n * ROWB2 + _kq * 16);\
            cp_async16(_d,        _pB + _n * 8 + _kq);                         \
            cp_async16(_d + BBUF, _pB + 512 + _n * 8 + _kq);                   \
        }                                                                      \
        asm volatile("cp.async.commit_group;" ::: "memory");                   \
    } while (0)

    int m0w = (wid & 3) * 32;        // warp M offset
    int n0w = (wid >> 2) * 32;       // warp N offset

    int q = lane >> 3, r = lane & 7;
    uint32_t aoff = (uint32_t)((m0w + (q & 1) * 8 + r) * PITCH + (q >> 1) * 8) * 2;
    uint32_t boff = (uint32_t)((n0w + (q >> 1) * 8 + r) * PITCH + (q & 1) * 8) * 2;

    float d[2][4][4];
    #pragma unroll
    for (int i = 0; i < 2; i++)
        #pragma unroll
        for (int j = 0; j < 4; j++)
            #pragma unroll
            for (int c = 0; c < 4; c++) d[i][j][c] = 0.0f;

    // ---- prologue: stage chunks 0 and 1 ----
    STAGE_CHUNK(0);
    if (nk > 1) STAGE_CHUNK(1);

    for (int kc = 0; kc < nk; kc++) {
        if (kc + 1 < nk)
            asm volatile("cp.async.wait_group 1;" ::: "memory");
        else
            asm volatile("cp.async.wait_group 0;" ::: "memory");
        __syncthreads();

        uint32_t ab = sb + (uint32_t)(kc & 1) * STAGE;
        uint32_t bb = ab + 2 * ABUF;
        #pragma unroll
        for (int ks = 0; ks < 4; ks++) {
            uint32_t ah[2][4], al[2][4];
            #pragma unroll
            for (int mt = 0; mt < 2; mt++) {
                uint32_t ao = aoff + (uint32_t)(mt * 16 * ROWB2 + ks * 32);
                ldm4(ah[mt], ab + ao);
                ldm4(al[mt], ab + ABUF + ao);
            }
            #pragma unroll
            for (int nt = 0; nt < 2; nt++) {
                uint32_t bo = boff + (uint32_t)(nt * 16 * ROWB2 + ks * 32);
                uint32_t bh[4], bl[4];
                ldm4(bh, bb + bo);
                ldm4(bl, bb + BBUF + bo);
                #pragma unroll
                for (int mt = 0; mt < 2; mt++) {
                    mma16816(d[mt][2*nt],   ah[mt], bh[0], bh[1]);
                    mma16816(d[mt][2*nt+1], ah[mt], bh[2], bh[3]);
                    mma16816(d[mt][2*nt],   ah[mt], bl[0], bl[1]);
                    mma16816(d[mt][2*nt+1], ah[mt], bl[2], bl[3]);
                    mma16816(d[mt][2*nt],   al[mt], bh[0], bh[1]);
                    mma16816(d[mt][2*nt+1], al[mt], bh[2], bh[3]);
                }
            }
        }
        __syncthreads();
        if (kc + 2 < nk) STAGE_CHUNK(kc + 2);
    }
    #undef STAGE_CHUNK

    // ---- epilogue: per-warp 32x32 ----
    int rq = lane >> 2, cq = lane & 3;
    #pragma unroll
    for (int mt = 0; mt < 2; mt++) {
        int row0 = brow + m0w + mt * 16 + rq;
        #pragma unroll
        for (int t8 = 0; t8 < 4; t8++) {
            int col = ntile * 64 + n0w + t8 * 8 + cq * 2;
            *(float2*)(C + (size_t)row0 * ldc + col)       = make_float2(d[mt][t8][0], d[mt][t8][1]);
            *(float2*)(C + (size_t)(row0 + 8) * ldc + col) = make_float2(d[mt][t8][2], d[mt][t8][3]);
        }
    }
}

// ------------------------- GRU elementwise -----------------------------------
__global__ void gru_kernel(const float* __restrict__ hprev,
                           const float* __restrict__ bi_, const float* __restrict__ bh_,
                           int last) {
    int node = blockIdx.x;
    int t    = threadIdx.x;
    float hv = hprev[(size_t)node * Hh + t];
    if (g_ncnt[node] > 0) {
        size_t base = (size_t)node * 3 * Hh;
        float gr  = g_gi[base + t]          + bi_[t]          + g_gh[base + t]          + bh_[t];
        float gz  = g_gi[base + Hh + t]     + bi_[Hh + t]     + g_gh[base + Hh + t]     + bh_[Hh + t];
        float gin = g_gi[base + 2 * Hh + t] + bi_[2 * Hh + t];
        float ghn = g_gh[base + 2 * Hh + t] + bh_[2 * Hh + t];
        float r = sigm_f(gr);
        float z = sigm_f(gz);
        float n = tanh_f(fmaf(r, ghn, gin));
        hv = (1.0f - z) * n + z * hv;
    }
    g_h[(size_t)node * Hh + t] = hv;
    uint16_t h, l; split2(hv, h, l);
    g_h_hi[(size_t)node * Hh + t] = __ushort_as_bfloat16(h);
    g_h_lo[(size_t)node * Hh + t] = __ushort_as_bfloat16(l);
    if (last) {
        g_xr_hi[(size_t)node * 256 + t] = __ushort_as_bfloat16(h);
        g_xr_lo[(size_t)node * 256 + t] = __ushort_as_bfloat16(l);
    }
}

// ------------------------- gated readout reduction ---------------------------
__global__ void readout_kernel(const float* __restrict__ bg, const float* __restrict__ bo,
                               float* __restrict__ out) {
    int b = blockIdx.x;
    int o = threadIdx.x;
    float acc = 0.0f;
    for (int i = 0; i < Nn; i++) {
        int node = b * Nn + i;
        if (g_ncnt[node] > 0) {
            float g = g_R[(size_t)node * 2 * NOUT + o]        + bg[o];
            float e = g_R[(size_t)node * 2 * NOUT + NOUT + o] + bo[o];
            acc = fmaf(sigm_f(g), e, acc);
        }
    }
    out[(size_t)b * NOUT + o] = acc;
}

// ------------------------- host orchestration --------------------------------
extern "C" void kernel_launch(void* const* d_in, const int* in_sizes, int n_in,
                              void* d_out, int out_size) {
    const float* nodes = (const float*)d_in[0];
    const float* edges = (const float*)d_in[1];
    const float* We    = (const float*)d_in[2];
    const float* Wn    = (const float*)d_in[3];
    const float* Wm    = (const float*)d_in[4];
    const float* Wi    = (const float*)d_in[5];
    const float* Wh    = (const float*)d_in[6];
    const float* bi_   = (const float*)d_in[7];
    const float* bh_   = (const float*)d_in[8];
    const float* Wg    = (const float*)d_in[9];
    const float* bg    = (const float*)d_in[10];
    const float* Wo    = (const float*)d_in[11];
    const float* bo    = (const float*)d_in[12];
    float* out = (float*)d_out;

    float *p_proj, *p_gi, *p_gh, *p_R;
    __nv_bfloat16 *p_hh, *p_hl, *p_mh, *p_ml, *p_xh, *p_xl, *p_wpr, *p_wih, *p_wro;
    cudaGetSymbolAddress((void**)&p_proj, g_proj);
    cudaGetSymbolAddress((void**)&p_gi,   g_gi);
    cudaGetSymbolAddress((void**)&p_gh,   g_gh);
    cudaGetSymbolAddress((void**)&p_R,    g_R);
    cudaGetSymbolAddress((void**)&p_hh,   g_h_hi);
    cudaGetSymbolAddress((void**)&p_hl,   g_h_lo);
    cudaGetSymbolAddress((void**)&p_mh,   g_msg_hi);
    cudaGetSymbolAddress((void**)&p_ml,   g_msg_lo);
    cudaGetSymbolAddress((void**)&p_xh,   g_xr_hi);
    cudaGetSymbolAddress((void**)&p_xl,   g_xr_lo);
    cudaGetSymbolAddress((void**)&p_wpr,  g_Wpr_img);
    cudaGetSymbolAddress((void**)&p_wih,  g_Wih_img);
    cudaGetSymbolAddress((void**)&p_wro,  g_Wro_img);

    float* p_h;
    cudaGetSymbolAddress((void**)&p_h, g_h);

    cudaFuncSetAttribute(gemm_tc, cudaFuncAttributeMaxDynamicSharedMemorySize, GEMM_SMEM);

    // prep
    prep_xr <<<(NODES * Hh + 255) / 256, 256>>>(nodes);
    prep_w  <<<196608 / 256, 256>>>(Wn, Wm, Wi, Wh, Wg, Wo);
    prep_graph<<<NODES, 64>>>(edges);

    const int ROWBCNT = NODES / 128;  // 160
    // initial projection: proj = h(=nodes) @ [Wn|Wm]  (4 n-tiles of 64)
    gemm_tc<<<dim3(4, ROWBCNT, 1), 256, GEMM_SMEM>>>(
        p_hh, p_hl, p_hh, p_hl, p_proj, p_proj, p_wpr, p_wpr, 128, 256);

    const float* hsrc = nodes;
    for (int p = 0; p < NPASS; p++) {
        attn_kernel<<<NODES, 128>>>(We);
        // gi = msg @ Wi (z=0), gh = h @ Wh (z=1): 6 n-tiles of 64
        gemm_tc<<<dim3(6, ROWBCNT, 2), 256, GEMM_SMEM>>>(
            p_mh, p_ml, p_hh, p_hl, p_gi, p_gh,
            p_wih, p_wih + (size_t)12 * 8192, 128, 384);
        gru_kernel<<<NODES, 128>>>(hsrc, bi_, bh_, (p == NPASS - 1) ? 1 : 0);
        hsrc = p_h;
        if (p < NPASS - 1) {
            gemm_tc<<<dim3(4, ROWBCNT, 1), 256, GEMM_SMEM>>>(
                p_hh, p_hl, p_hh, p_hl, p_proj, p_proj, p_wpr, p_wpr, 128, 256);
        }
    }

    // readout: R = [h|nodes] @ [Wg|Wo]  (K=256 -> 4 chunks, 4 n-tiles)
    gemm_tc<<<dim3(4, ROWBCNT, 1), 256, GEMM_SMEM>>>(
        p_xh, p_xl, p_xh, p_xl, p_R, p_R, p_wro, p_wro, 256, 256);
    readout_kernel<<<Bb, 128>>>(bg, bo, out);
    (void)in_sizes; (void)n_in; (void)out_size;
}